// round 9
// baseline (speedup 1.0000x reference)
#include <cuda_runtime.h>
#include <cstdint>
#include <cstring>

#define NTOT 2048
#define JROWS 288
#define EPSV 1e-6f

typedef unsigned int  u32;
typedef unsigned long long u64;
typedef unsigned short u16;

// ---------------- fp32 scratch ----------------
static __device__ __align__(16) float g_part[2097152];   // split-K partials (8 MB)
static __device__ __align__(16) float g_Hraw[NTOT * 128];
static __device__ __align__(16) float g_H   [NTOT * 128];
static __device__ __align__(16) float g_logH[NTOT * 128];
static __device__ __align__(16) float g_jpart[JROWS * 128];
static __device__ __align__(16) float g_w   [128];

// ---------------- bf16 split scratch ----------------
static __device__ __align__(16) u16 XH [2*262144], XL [2*262144];   // x row-major
static __device__ __align__(16) u16 XTH[2*262144], XTL[2*262144];   // x^T [128,2048]
static __device__ __align__(16) u16 W1TH[4*262144], W1TL[4*262144]; // W1^T [128,2048]
static __device__ __align__(16) u16 W2TH[4*16384],  W2TL[4*16384];
static __device__ __align__(16) u16 FW1TH[65536],   FW1TL[65536];   // fW1^T [128,512]
static __device__ __align__(16) u16 FW2TH[16384],   FW2TL[16384];
static __device__ __align__(16) u16 THTH[2*16384],  THTL[2*16384];
static __device__ __align__(16) u16 MTH[4*16384],   MTL[4*16384];
static __device__ __align__(16) u16 P1H[4*16384],   P1L[4*16384];
static __device__ __align__(16) u16 HCH[NTOT*512],  HCL[NTOT*512];
static __device__ __align__(16) u16 HTMH[262144],   HTML[262144];
static __device__ __align__(16) u16 HH [262144],    HL [262144];
static __device__ __align__(16) u16 HTH[262144],    HTL[262144];    // H^T
static __device__ __align__(16) u16 YTH[2*262144],  YTL[2*262144];  // Y^T
static __device__ __align__(16) u16 ZWTH[2*16384],  ZWTL[2*16384];

// ---------------- bf16 helpers ----------------
__device__ __forceinline__ u16 f2bf(float v) {
    u32 x = __float_as_uint(v);
    x += 0x7FFFu + ((x >> 16) & 1u);
    return (u16)(x >> 16);
}
__device__ __forceinline__ float bf2f(u16 h) { return __uint_as_float(((u32)h) << 16); }
__device__ __forceinline__ void bf_split(float v, u16& h, u16& l) {
    h = f2bf(v); l = f2bf(v - bf2f(h));
}

// ---------------- PTX helpers ----------------
__device__ __forceinline__ u32 smem_u32(const void* p) {
    u32 a;
    asm("{ .reg .u64 t; cvta.to.shared.u64 t, %1; cvt.u32.u64 %0, t; }" : "=r"(a) : "l"(p));
    return a;
}
#define STS128U(addr, v) \
    asm volatile("st.shared.v4.b32 [%0], {%1,%2,%3,%4};" :: "r"(addr), "r"((v).x), "r"((v).y), "r"((v).z), "r"((v).w) : "memory")
#define SW128(o) ((o) ^ (((o) >> 3) & 0x70))

__device__ __forceinline__ void ldm4(u32* r, u32 addr) {
    asm volatile("ldmatrix.sync.aligned.m8n8.x4.shared.b16 {%0,%1,%2,%3}, [%4];"
                 : "=r"(r[0]), "=r"(r[1]), "=r"(r[2]), "=r"(r[3]) : "r"(addr));
}
__device__ __forceinline__ void mmabf(float* c, const u32* a, u32 b0, u32 b1) {
    asm volatile("mma.sync.aligned.m16n8k16.row.col.f32.bf16.bf16.f32 "
        "{%0,%1,%2,%3}, {%4,%5,%6,%7}, {%8,%9}, {%0,%1,%2,%3};"
        : "+f"(c[0]), "+f"(c[1]), "+f"(c[2]), "+f"(c[3])
        : "r"(a[0]), "r"(a[1]), "r"(a[2]), "r"(a[3]), "r"(b0), "r"(b1));
}

// ================= generic tensor-core GEMM =================
// D[128,128](fp32) = sum_k (AH+AL)[m,k]*(BH+BL)[n,k] (3 split products), K-major ops.
// grid (Mtiles, Kchunks, Z), 256 threads (8 warps, each 64x32 out block).
struct MmaP {
    const u16 *AH[4], *AL[4], *BH[4], *BL[4];
    float* outF[4];
    u16 *oH[4], *oL[4];
    const float* aux[4];
    int ldA, ldB, ldO, Kchunk, chunkStride, mode;
};

__global__ void __launch_bounds__(256) k_mma(MmaP p) {
    extern __shared__ __align__(16) char dyn[];
    u32 sbase = smem_u32(dyn);

    int z = blockIdx.z, by = blockIdx.y;
    int mBase = blockIdx.x * 128;
    int kBeg = by * p.Kchunk;
    int nslab = p.Kchunk >> 5;
    int tid = threadIdx.x, lane = tid & 31, wid = tid >> 5;
    int wm = wid & 1, wn = wid >> 1;

    // loader role: threads 0-127 load A rows, 128-255 load B rows
    int lrow = tid & 127;
    bool isA = tid < 128;
    const u16* srcH = isA ? p.AH[z] + (size_t)(mBase + lrow) * p.ldA + kBeg
                          : p.BH[z] + (size_t)lrow * p.ldB + kBeg;
    const u16* srcL = isA ? p.AL[z] + (size_t)(mBase + lrow) * p.ldA + kBeg
                          : p.BL[z] + (size_t)lrow * p.ldB + kBeg;
    u32 bufOff = isA ? 0u : 16384u;
    u32 rowo = (u32)lrow * 128u;

    float acc[4][4][4];
#pragma unroll
    for (int t = 0; t < 4; t++)
#pragma unroll
        for (int n = 0; n < 4; n++)
#pragma unroll
            for (int q = 0; q < 4; q++) acc[t][n][q] = 0.f;

    uint4 rh[4], rl[4];
    auto LDG = [&](int s) {
        const uint4* ph = (const uint4*)(srcH + s * 32);
        const uint4* pl = (const uint4*)(srcL + s * 32);
#pragma unroll
        for (int j = 0; j < 4; j++) { rh[j] = ph[j]; rl[j] = pl[j]; }
    };
    auto STS = [&](int buf) {
        u32 b = sbase + (u32)buf * 32768u + bufOff;
#pragma unroll
        for (int j = 0; j < 4; j++) {
            STS128U(b + SW128(rowo + j * 16u), rh[j]);
            STS128U(b + SW128(rowo + 64u + j * 16u), rl[j]);
        }
    };
    auto COMPUTE = [&](int buf) {
        u32 tA = sbase + (u32)buf * 32768u;
        u32 tB = tA + 16384u;
#pragma unroll
        for (int kk = 0; kk < 2; kk++) {
            u32 colh = (u32)kk * 32u + (u32)((lane >> 4) << 4);
            u32 bh[8], bl[8];
#pragma unroll
            for (int pp = 0; pp < 2; pp++) {
                u32 nr = (u32)(wn * 32 + pp * 16 + (lane & 15));
                ldm4(bh + pp * 4, tB + SW128(nr * 128u + colh));
                ldm4(bl + pp * 4, tB + SW128(nr * 128u + 64u + colh));
            }
#pragma unroll
            for (int t = 0; t < 4; t++) {
                u32 ah[4], al[4];
                u32 mr = (u32)(wm * 64 + t * 16 + (lane & 15));
                ldm4(ah, tA + SW128(mr * 128u + colh));
                ldm4(al, tA + SW128(mr * 128u + 64u + colh));
                // n-tile frag pairs: n0:{bh0,bh2} n1:{bh1,bh3} n2:{bh4,bh6} n3:{bh5,bh7}
                mmabf(acc[t][0], ah, bh[0], bh[2]);
                mmabf(acc[t][0], ah, bl[0], bl[2]);
                mmabf(acc[t][0], al, bh[0], bh[2]);
                mmabf(acc[t][1], ah, bh[1], bh[3]);
                mmabf(acc[t][1], ah, bl[1], bl[3]);
                mmabf(acc[t][1], al, bh[1], bh[3]);
                mmabf(acc[t][2], ah, bh[4], bh[6]);
                mmabf(acc[t][2], ah, bl[4], bl[6]);
                mmabf(acc[t][2], al, bh[4], bh[6]);
                mmabf(acc[t][3], ah, bh[5], bh[7]);
                mmabf(acc[t][3], ah, bl[5], bl[7]);
                mmabf(acc[t][3], al, bh[5], bh[7]);
            }
        }
    };

    LDG(0); STS(0); __syncthreads();
#pragma unroll 1
    for (int s = 0; s < nslab; s++) {
        if (s + 1 < nslab) LDG(s + 1);
        COMPUTE(s & 1);
        if (s + 1 < nslab) { STS((s + 1) & 1); __syncthreads(); }
    }
    __syncthreads();

    // ---------- dump acc -> smem fp32 [128][129] ----------
    float* smF = (float*)dyn;
#pragma unroll
    for (int t = 0; t < 4; t++)
#pragma unroll
        for (int n = 0; n < 4; n++) {
            int r = wm * 64 + t * 16 + (lane >> 2);
            int c = wn * 32 + n * 8 + ((lane & 3) << 1);
            smF[r * 129 + c]           = acc[t][n][0];
            smF[r * 129 + c + 1]       = acc[t][n][1];
            smF[(r + 8) * 129 + c]     = acc[t][n][2];
            smF[(r + 8) * 129 + c + 1] = acc[t][n][3];
        }
    __syncthreads();

    // ---------- writeback ----------
    if (p.mode == 2 || p.mode == 3) {          // transposed bf16 split
#pragma unroll 4
        for (int q = 0; q < 64; q++) {
            int idx = q * 256 + tid;
            int r = idx & 127, n = idx >> 7;
            float v = smF[r * 129 + n];
            if (p.mode == 3) v += p.aux[z][n];
            u16 h, l; bf_split(v, h, l);
            size_t o = (size_t)n * p.ldO + mBase + r;
            p.oH[z][o] = h; p.oL[z][o] = l;
        }
    } else {
#pragma unroll 4
        for (int q = 0; q < 64; q++) {
            int idx = q * 256 + tid;
            int r = idx >> 7, c = idx & 127;
            float v = smF[r * 129 + c];
            size_t grow = (size_t)(mBase + r);
            if (p.mode == 0) {
                p.outF[z][(size_t)by * p.chunkStride + grow * 128 + c] = v;
            } else if (p.mode == 1) {
                u16 h, l; bf_split(v, h, l);
                p.oH[z][grow * p.ldO + c] = h; p.oL[z][grow * p.ldO + c] = l;
            } else if (p.mode == 4) {
                p.outF[z][grow * 128 + c] = v + p.aux[z][c];
            } else {                           // 5: residual + elu
                float x = p.aux[z][grow * 128 + c];
                p.outF[z][grow * 128 + c] = x + ((v > 0.f) ? v : expm1f(v));
            }
        }
    }
}

// ================= transpose + bf16-split conversion =================
__device__ __forceinline__ void tconv(const float* __restrict__ src, int Ksrc, int tileRow,
                                      u16* dH, u16* dL, u16* tH, u16* tL)
{
    __shared__ u16 sh[32][136], sl[32][136];
    int tid = threadIdx.x;
    for (int i = tid; i < 32 * 128; i += 256) {
        int r = i >> 7, c = i & 127;
        float v = src[(size_t)(tileRow + r) * 128 + c];
        u16 h, l; bf_split(v, h, l);
        if (dH) { dH[(size_t)(tileRow + r) * 128 + c] = h; dL[(size_t)(tileRow + r) * 128 + c] = l; }
        sh[r][c] = h; sl[r][c] = l;
    }
    __syncthreads();
    for (int i = tid; i < 128 * 32; i += 256) {
        int rt = i >> 5, ct = i & 31;
        size_t o = (size_t)rt * Ksrc + tileRow + ct;
        tH[o] = sh[ct][rt]; tL[o] = sl[ct][rt];
    }
}

__global__ __launch_bounds__(256) void k_convX(const float* __restrict__ xt, const float* __restrict__ xn)
{
    int side = blockIdx.y;
    const float* src = side ? xn : xt;
    size_t off = (size_t)side * 262144;
    tconv(src, NTOT, blockIdx.x * 32, XH + off, XL + off, XTH + off, XTL + off);
}

struct WPtrs { const float* s[12]; };
__global__ __launch_bounds__(256) void k_convW(WPtrs wp)
{
    const int tilesC[13] = {0, 64, 128, 192, 256, 260, 264, 268, 272, 288, 292, 296, 300};
    int b = blockIdx.x, idx = 0;
    while (b >= tilesC[idx + 1]) idx++;
    int lt = b - tilesC[idx];
    u16 *tH, *tL; int K;
    if (idx < 4)      { K = 2048; tH = W1TH + idx * 262144;      tL = W1TL + idx * 262144; }
    else if (idx < 8) { K = 128;  tH = W2TH + (idx - 4) * 16384; tL = W2TL + (idx - 4) * 16384; }
    else if (idx == 8){ K = 512;  tH = FW1TH;                    tL = FW1TL; }
    else if (idx == 9){ K = 128;  tH = FW2TH;                    tL = FW2TL; }
    else              { K = 128;  tH = THTH + (idx - 10) * 16384; tL = THTL + (idx - 10) * 16384; }
    tconv(wp.s[idx], K, lt * 32, nullptr, nullptr, tH, tL);
}

__global__ __launch_bounds__(256) void k_convH()
{
    tconv(g_H, NTOT, blockIdx.x * 32, HH, HL, HTH, HTL);
}

// ================= reductions =================
__global__ __launch_bounds__(256) void k_redP1(const float* __restrict__ b0, const float* __restrict__ b1,
                                               const float* __restrict__ b2, const float* __restrict__ b3)
{
    int z = blockIdx.y;
    int i = blockIdx.x * 256 + threadIdx.x;              // < 16384
    const float* b = (z == 0) ? b0 : (z == 1) ? b1 : (z == 2) ? b2 : b3;
    float s = b[i & 127];
#pragma unroll
    for (int c = 0; c < 32; c++) s += g_part[(size_t)z * 524288 + (size_t)c * 16384 + i];
    s = fmaxf(s, 0.f);
    u16 h, l; bf_split(s, h, l);
    P1H[z * 16384 + i] = h; P1L[z * 16384 + i] = l;
}

__global__ __launch_bounds__(256) void k_redHtmp(const float* __restrict__ fb1)
{
    int i = blockIdx.x * 256 + threadIdx.x;              // < 262144
    float s = fb1[i & 127];
#pragma unroll
    for (int c = 0; c < 8; c++) s += g_part[(size_t)c * 262144 + i];
    s = fmaxf(s, 0.f);
    u16 h, l; bf_split(s, h, l);
    HTMH[i] = h; HTML[i] = l;
}

__global__ __launch_bounds__(256) void k_redZW()
{
    int z = blockIdx.y;
    int i = blockIdx.x * 256 + threadIdx.x;              // < 16384
    float s = 0.f;
#pragma unroll
    for (int c = 0; c < 32; c++) s += g_part[(size_t)z * 524288 + (size_t)c * 16384 + i];
    s *= g_w[i & 127];
    u16 h, l; bf_split(s, h, l);
    ZWTH[z * 16384 + i] = h; ZWTL[z * 16384 + i] = l;
}

// ================= block reductions =================
template <int NW>
__device__ __forceinline__ float block_sum(float v) {
    __shared__ float sred[8];
    __syncthreads();
#pragma unroll
    for (int o = 16; o; o >>= 1) v += __shfl_xor_sync(0xffffffffu, v, o);
    if ((threadIdx.x & 31) == 0) sred[threadIdx.x >> 5] = v;
    __syncthreads();
    float t = 0.f;
#pragma unroll
    for (int k = 0; k < NW; k++) t += sred[k];
    return t;
}
template <int NW>
__device__ __forceinline__ float block_max(float v) {
    __shared__ float sred[8];
    __syncthreads();
#pragma unroll
    for (int o = 16; o; o >>= 1) v = fmaxf(v, __shfl_xor_sync(0xffffffffu, v, o));
    if ((threadIdx.x & 31) == 0) sred[threadIdx.x >> 5] = v;
    __syncthreads();
    float t = -3.4e38f;
#pragma unroll
    for (int k = 0; k < NW; k++) t = fmaxf(t, sred[k]);
    return t;
}

// ================= column standardize + softmax =================
__global__ __launch_bounds__(256) void k_colsm()
{
    int e = blockIdx.x;
    __shared__ float s[NTOT];
    int tid = threadIdx.x;
    for (int n = tid; n < NTOT; n += 256) s[n] = g_Hraw[n * 128 + e];
    __syncthreads();
    float lsum = 0.f;
    for (int n = tid; n < NTOT; n += 256) lsum += s[n];
    float mean = block_sum<8>(lsum) * (1.f / NTOT);
    float lss = 0.f;
    for (int n = tid; n < NTOT; n += 256) { float d = s[n] - mean; lss += d * d; }
    float var = block_sum<8>(lss) * (1.f / (NTOT - 1));
    float inv = 1.f / (sqrtf(var) + EPSV);
    float lmax = -3.4e38f;
    for (int n = tid; n < NTOT; n += 256) {
        float z = (s[n] - mean) * inv;
        s[n] = z;
        lmax = fmaxf(lmax, z);
    }
    __syncthreads();
    float mx = block_max<8>(lmax);
    float lse = 0.f;
    for (int n = tid; n < NTOT; n += 256) lse += __expf(s[n] - mx);
    float sum = block_sum<8>(lse);
    float invs = 1.f / sum;
    float lls = __logf(sum);
    for (int n = tid; n < NTOT; n += 256) {
        float z = s[n];
        g_H[n * 128 + e]    = __expf(z - mx) * invs;
        g_logH[n * 128 + e] = (z - mx) - lls;
    }
}

// ================= pairwise JSD =================
__global__ __launch_bounds__(256) void k_jsd()
{
    int t = blockIdx.x;
    int bi = 0, rem = t;
    while (rem >= 8 - bi) { rem -= 8 - bi; bi++; }
    int bj = bi + rem;
    int tid = threadIdx.x;
    int ti = tid & 15, tj = tid >> 4;
    int i = bi * 16 + ti, j = bj * 16 + tj;
    __shared__ float sHi[16][16], sLi[16][16], sHj[16][16], sLj[16][16];
    float acci = 0.f, accj = 0.f;
    int lr = tid >> 4, lc = tid & 15;
    int nBeg = blockIdx.y * 256;
    for (int n0 = nBeg; n0 < nBeg + 256; n0 += 16) {
        __syncthreads();
        int n = n0 + lr;
        sHi[lr][lc] = g_H   [n * 128 + bi * 16 + lc];
        sLi[lr][lc] = g_logH[n * 128 + bi * 16 + lc];
        sHj[lr][lc] = g_H   [n * 128 + bj * 16 + lc];
        sLj[lr][lc] = g_logH[n * 128 + bj * 16 + lc];
        __syncthreads();
#pragma unroll
        for (int r = 0; r < 16; r++) {
            float hi = sHi[r][ti], hj = sHj[r][tj];
            float m  = 0.5f * (hi + hj);
            float lm = __logf(m);
            acci += hi * (sLi[r][ti] - lm);
            accj += hj * (sLj[r][tj] - lm);
        }
    }
    float v = (i < j) ? 0.5f * (acci + accj) : 0.f;
    __shared__ float red[16][16];
    __syncthreads();
    red[tj][ti] = v;
    __syncthreads();
    float* out = g_jpart + (size_t)(blockIdx.y * 36 + blockIdx.x) * 128;
    if (tid < 128) out[tid] = 0.f;
    __syncthreads();
    if (tid < 16) {
        float si = 0.f, sj = 0.f;
#pragma unroll
        for (int r = 0; r < 16; r++) { si += red[r][tid]; sj += red[tid][r]; }
        out[bi * 16 + tid] += si;
        out[bj * 16 + tid] += sj;
    }
}

__global__ __launch_bounds__(128) void k_w()
{
    int e = threadIdx.x;
    float cs = 0.f;
    for (int r = 0; r < JROWS; r++) cs += g_jpart[r * 128 + e];
    float jm = cs * (1.f / 128.f);
    float mean = block_sum<4>(jm) * (1.f / 128.f);
    float d = jm - mean;
    float var = block_sum<4>(d * d) * (1.f / 127.f);
    float njm = d / (sqrtf(var) + EPSV);
    float mx = block_max<4>(njm);
    float ex = __expf(njm - mx);
    float sum = block_sum<4>(ex);
    g_w[e] = ex / sum;
}

// ================= host =================
static inline void* dsym(const void* s) { void* p = nullptr; cudaGetSymbolAddress(&p, s); return p; }

extern "C" void kernel_launch(void* const* d_in, const int* in_sizes, int n_in,
                              void* d_out, int out_size)
{
    const float* xt  = (const float*)d_in[0];
    const float* xn  = (const float*)d_in[1];
    const float* W1[4]  = {(const float*)d_in[2],  (const float*)d_in[6],  (const float*)d_in[10], (const float*)d_in[14]};
    const float* B1[4]  = {(const float*)d_in[3],  (const float*)d_in[7],  (const float*)d_in[11], (const float*)d_in[15]};
    const float* W2[4]  = {(const float*)d_in[4],  (const float*)d_in[8],  (const float*)d_in[12], (const float*)d_in[16]};
    const float* B2[4]  = {(const float*)d_in[5],  (const float*)d_in[9],  (const float*)d_in[13], (const float*)d_in[17]};
    const float* fW1 = (const float*)d_in[18];
    const float* fb1 = (const float*)d_in[19];
    const float* fW2 = (const float*)d_in[20];
    const float* fb2 = (const float*)d_in[21];
    const float* thT = (const float*)d_in[22];
    const float* thN = (const float*)d_in[23];
    float* out = (float*)d_out;

    static const int SMEM = 66560;
    cudaFuncSetAttribute(k_mma, cudaFuncAttributeMaxDynamicSharedMemorySize, SMEM);

    u16 *xh = (u16*)dsym(XH), *xl = (u16*)dsym(XL), *xth = (u16*)dsym(XTH), *xtl = (u16*)dsym(XTL);
    u16 *w1h = (u16*)dsym(W1TH), *w1l = (u16*)dsym(W1TL), *w2h = (u16*)dsym(W2TH), *w2l = (u16*)dsym(W2TL);
    u16 *f1h = (u16*)dsym(FW1TH), *f1l = (u16*)dsym(FW1TL), *f2h = (u16*)dsym(FW2TH), *f2l = (u16*)dsym(FW2TL);
    u16 *thh = (u16*)dsym(THTH), *thl = (u16*)dsym(THTL);
    u16 *mth = (u16*)dsym(MTH), *mtl = (u16*)dsym(MTL), *p1h = (u16*)dsym(P1H), *p1l = (u16*)dsym(P1L);
    u16 *hch = (u16*)dsym(HCH), *hcl = (u16*)dsym(HCL), *htmh = (u16*)dsym(HTMH), *html = (u16*)dsym(HTML);
    u16 *hh = (u16*)dsym(HH), *hl = (u16*)dsym(HL), *hth = (u16*)dsym(HTH), *htl = (u16*)dsym(HTL);
    u16 *yth = (u16*)dsym(YTH), *ytl = (u16*)dsym(YTL), *zwh = (u16*)dsym(ZWTH), *zwl = (u16*)dsym(ZWTL);
    float* gp = (float*)dsym(g_part);
    float* ghraw = (float*)dsym(g_Hraw);

    // conversions
    k_convX<<<dim3(64, 2), 256>>>(xt, xn);
    WPtrs wp;
    for (int i = 0; i < 4; i++) { wp.s[i] = W1[i]; wp.s[4 + i] = W2[i]; }
    wp.s[8] = fW1; wp.s[9] = fW2; wp.s[10] = thT; wp.s[11] = thN;
    k_convW<<<300, 256>>>(wp);

    MmaP p;

    // part1: P = X^T @ W1 per head (A=XT, B=W1T), split-K 32 x 64
    memset(&p, 0, sizeof(p));
    for (int z = 0; z < 4; z++) {
        int sideA = (z == 0 || z == 3) ? 0 : 1;
        p.AH[z] = xth + sideA * 262144; p.AL[z] = xtl + sideA * 262144;
        p.BH[z] = w1h + z * 262144;     p.BL[z] = w1l + z * 262144;
        p.outF[z] = gp + (size_t)z * 524288;
    }
    p.ldA = 2048; p.ldB = 2048; p.Kchunk = 64; p.chunkStride = 16384; p.mode = 0;
    k_mma<<<dim3(1, 32, 4), 256, SMEM>>>(p);

    k_redP1<<<dim3(64, 4), 256>>>(B1[0], B1[1], B1[2], B1[3]);

    // M = P1 @ W2 + b2 -> MT (mode3 transposed)
    memset(&p, 0, sizeof(p));
    for (int z = 0; z < 4; z++) {
        p.AH[z] = p1h + z * 16384; p.AL[z] = p1l + z * 16384;
        p.BH[z] = w2h + z * 16384; p.BL[z] = w2l + z * 16384;
        p.oH[z] = mth + z * 16384; p.oL[z] = mtl + z * 16384;
        p.aux[z] = B2[z];
    }
    p.ldA = 128; p.ldB = 128; p.ldO = 128; p.Kchunk = 128; p.mode = 3;
    k_mma<<<dim3(1, 1, 4), 256, SMEM>>>(p);

    // Hcat = X @ M (mode1 row-major bf16 split, ldO 512, col offset z*128)
    memset(&p, 0, sizeof(p));
    for (int z = 0; z < 4; z++) {
        int sideA = (z == 0 || z == 2) ? 0 : 1;
        p.AH[z] = xh + sideA * 262144; p.AL[z] = xl + sideA * 262144;
        p.BH[z] = mth + z * 16384;     p.BL[z] = mtl + z * 16384;
        p.oH[z] = hch + z * 128;       p.oL[z] = hcl + z * 128;
    }
    p.ldA = 128; p.ldB = 128; p.ldO = 512; p.Kchunk = 128; p.mode = 1;
    k_mma<<<dim3(16, 1, 4), 256, SMEM>>>(p);

    // f1 partials: Hcat @ fW1, split-K 8 x 64
    memset(&p, 0, sizeof(p));
    p.AH[0] = hch; p.AL[0] = hcl; p.BH[0] = f1h; p.BL[0] = f1l;
    p.outF[0] = gp;
    p.ldA = 512; p.ldB = 512; p.Kchunk = 64; p.chunkStride = 262144; p.mode = 0;
    k_mma<<<dim3(16, 8, 1), 256, SMEM>>>(p);

    k_redHtmp<<<1024, 256>>>(fb1);

    // f2: Hraw = Htmp @ fW2 + fb2 (mode4 fp32)
    memset(&p, 0, sizeof(p));
    p.AH[0] = htmh; p.AL[0] = html; p.BH[0] = f2h; p.BL[0] = f2l;
    p.outF[0] = ghraw; p.aux[0] = fb2;
    p.ldA = 128; p.ldB = 128; p.Kchunk = 128; p.mode = 4;
    k_mma<<<dim3(16, 1, 1), 256, SMEM>>>(p);

    k_colsm<<<128, 256>>>();
    k_convH<<<64, 256>>>();
    k_jsd<<<dim3(36, 8), 256>>>();
    k_w<<<1, 128>>>();

    // Y = x @ theta -> YT (mode2 transposed, ldO 2048)
    memset(&p, 0, sizeof(p));
    for (int z = 0; z < 2; z++) {
        p.AH[z] = xh + z * 262144;  p.AL[z] = xl + z * 262144;
        p.BH[z] = thh + z * 16384;  p.BL[z] = thl + z * 16384;
        p.oH[z] = yth + z * 262144; p.oL[z] = ytl + z * 262144;
    }
    p.ldA = 128; p.ldB = 128; p.ldO = 2048; p.Kchunk = 128; p.mode = 2;
    k_mma<<<dim3(16, 1, 2), 256, SMEM>>>(p);

    // ZT[d,e] = sum_n Y[n,d] H[n,e]  (A=YT, B=HT), split-K 32 x 64
    memset(&p, 0, sizeof(p));
    for (int z = 0; z < 2; z++) {
        p.AH[z] = yth + z * 262144; p.AL[z] = ytl + z * 262144;
        p.BH[z] = hth;              p.BL[z] = htl;
        p.outF[z] = gp + (size_t)z * 524288;
    }
    p.ldA = 2048; p.ldB = 2048; p.Kchunk = 64; p.chunkStride = 16384; p.mode = 0;
    k_mma<<<dim3(1, 32, 2), 256, SMEM>>>(p);

    k_redZW<<<dim3(64, 2), 256>>>();

    // final: out = x + elu(H @ Zw^T)  (A=H row-major, B=ZWT)
    memset(&p, 0, sizeof(p));
    for (int z = 0; z < 2; z++) {
        p.AH[z] = hh; p.AL[z] = hl;
        p.BH[z] = zwh + z * 16384; p.BL[z] = zwl + z * 16384;
        p.outF[z] = out + (size_t)z * 262144;
        p.aux[z] = z ? xn : xt;
    }
    p.ldA = 128; p.ldB = 128; p.Kchunk = 128; p.mode = 5;
    k_mma<<<dim3(16, 1, 2), 256, SMEM>>>(p);
}